// round 14
// baseline (speedup 1.0000x reference)
#include <cuda_runtime.h>
#include <cuda_fp16.h>
#include <cstdint>

#define WID 256
#define HGT 256
#define HW  65536
#define BATCH 8
#define BHW 524288

// ---------------- scratch ----------------
__device__ __half g_actAh[(size_t)BATCH * HW * 32];  // conv1 out (half, NHWC)
__device__ __half g_actBh[(size_t)BATCH * HW * 64];  // conv2 out (half, NHWC)
__device__ __half g_actCh[(size_t)BATCH * HW * 32];  // conv3 out (half, NHWC)
__device__ __half g_w2p[9 * 2 * 2 * 512];            // conv2 w packed (tap,kk,nh) 1KB blocks
__device__ __half g_w3p[2 * 9 * 2 * 2 * 256];        // conv3 w packed (h,tap,kk,nh) 512B blocks

// ---------------- helpers ----------------
#define MMA_F16(d, a, b0, b1) \
    asm volatile("mma.sync.aligned.m16n8k16.row.col.f32.f16.f16.f32 " \
        "{%0,%1,%2,%3}, {%4,%5,%6,%7}, {%8,%9}, {%0,%1,%2,%3};" \
        : "+f"((d)[0]), "+f"((d)[1]), "+f"((d)[2]), "+f"((d)[3]) \
        : "r"((a)[0]), "r"((a)[1]), "r"((a)[2]), "r"((a)[3]), "r"(b0), "r"(b1))

// ---------------- weight pack: fp16, exact fragment order ----------------
__global__ void __launch_bounds__(256) w_pack_k(
    const float* __restrict__ w2, const float* __restrict__ w3,
    __half* __restrict__ p2, __half* __restrict__ p3)
{
    int idx = blockIdx.x * 256 + threadIdx.x;   // < 36864
    if (idx < 18432) {   // conv2: nh-split (N=32 per warp), 1KB blocks
        int e = idx & 7, lane = (idx >> 3) & 31;
        int blk = (idx >> 8) & 1, nh = (idx >> 9) & 1;
        int kk = (idx >> 10) & 1, tap = idx >> 11;
        int qid = lane >> 2, tig = lane & 3;
        int nt = blk * 2 + (e >> 2), breg = (e >> 1) & 1, lo = e & 1;
        int k = kk * 16 + breg * 8 + 2 * tig + lo;
        int n = nh * 32 + nt * 8 + qid;
        p2[((((tap * 2 + kk) * 2 + nh) * 2 + blk) * 32 + lane) * 8 + e] =
            __float2half_rn(w2[((size_t)n * 32 + k) * 9 + tap]);
    }
    {   // conv3: nh-split (N=16 per warp), cin-half h, 512B blocks
        int h = idx / 18432, r = idx % 18432;
        int r2 = r % 9216;                 // dup-write harmless
        int tap = r2 / 1024, r3 = r2 - tap * 1024;
        int kk = (r3 >> 9) & 1, nh = (r3 >> 8) & 1;
        int lane = (r3 >> 3) & 31, e = r3 & 7;
        int qid = lane >> 2, tig = lane & 3;
        int ntl = e >> 2, breg = (e >> 1) & 1, lo = e & 1;
        int k = h * 32 + kk * 16 + breg * 8 + 2 * tig + lo;
        int n = nh * 16 + ntl * 8 + qid;
        p3[((((h * 9 + tap) * 2 + kk) * 2 + nh) * 32 + lane) * 8 + e] =
            __float2half_rn(w3[((size_t)n * 64 + k) * 9 + tap]);
    }
}

// ---------------- fused prep + conv1 (half out) ----------------
__global__ void __launch_bounds__(256) fuse_pc1_k(
    const float* __restrict__ inp, const float* __restrict__ H0,
    const float* __restrict__ C0, const float* __restrict__ c2,
    const float* __restrict__ sf, const float* __restrict__ w1,
    const float* __restrict__ b1, float* __restrict__ out,
    __half* __restrict__ actA)
{
    __shared__ float s_in[324];
    __shared__ float s_vs[324];
    __shared__ float sw[288];
    __shared__ float sb[32];

    const int tid = threadIdx.x;
    const int b = blockIdx.z, x0 = blockIdx.x * 16, y0 = blockIdx.y * 16;

    for (int i = tid; i < 288; i += 256) sw[i] = w1[i];
    if (tid < 32) sb[tid] = b1[tid];
    const float sfv = sf[0];

    for (int i = tid; i < 324; i += 256) {
        int yy = i / 18, xx = i - yy * 18;
        int gy = y0 - 1 + yy, gx = x0 - 1 + xx;
        float iv = 0.f, vsv = 0.f;
        if ((unsigned)gy < HGT && (unsigned)gx < WID) {
            int gidx = (b << 16) + (gy << 8) + gx;
            iv  = inp[gidx];
            vsv = (iv - H0[gidx]) / sfv;
        }
        s_in[i] = iv;
        s_vs[i] = vsv;
    }
    __syncthreads();

    const int py = tid >> 4, px = tid & 15;
    const int y = y0 + py, x = x0 + px;
    const int si = (py + 1) * 18 + px + 1;
    const int rem = (y << 8) + x;
    const int idx = (b << 16) + rem;

    float cc  = s_in[si];
    float lap = s_in[si - 18] + s_in[si + 18] + s_in[si - 1] + s_in[si + 1] - 4.f * cc;
    float c0v = C0[(size_t)b * 2 * HW + rem];
    float Hv  = 2.f * cc - c0v + c2[0] * lap;
    float V   = cc - H0[idx];

    out[(size_t)BHW + idx]     = Hv;
    out[4 * (size_t)BHW + idx] = V;
    out[2 * (size_t)BHW + (size_t)b * 2 * HW + rem]      = cc;
    out[2 * (size_t)BHW + (size_t)b * 2 * HW + HW + rem] = c0v;

    float xv[9];
    #pragma unroll
    for (int t = 0; t < 9; t++)
        xv[t] = s_vs[(py + t / 3) * 18 + px + t % 3];

    __half2* op = (__half2*)(actA + (size_t)idx * 32);
    #pragma unroll
    for (int c2i = 0; c2i < 16; c2i++) {
        float v[2];
        #pragma unroll
        for (int u = 0; u < 2; u++) {
            int co = c2i * 2 + u;
            float acc = sb[co];
            #pragma unroll
            for (int t = 0; t < 9; t++) acc = fmaf(xv[t], sw[co * 9 + t], acc);
            v[u] = fmaxf(acc, 0.f);
        }
        op[c2i] = __floats2half2_rn(v[0], v[1]);
    }
}

// ---------------- conv2: 32->64 fp16 mma k16, 1024 thr, n-split (R13, proven) ----------------
__global__ void __launch_bounds__(1024, 1) conv2_mma(
    const __half* __restrict__ in, const __half* __restrict__ wp,
    const float* __restrict__ bias, __half* __restrict__ outp)
{
    constexpr int AS = 40;
    extern __shared__ char smraw[];
    __half* s_act = (__half*)smraw;          // 48960 B
    char*   s_wb  = smraw + 48960;           // 36864 B

    const int tid = threadIdx.x;
    const int b   = blockIdx.z;
    const int x0  = blockIdx.x * 32;
    const int y0  = blockIdx.y * 16;

    const __half* inb = in + (size_t)b * HW * 32;
    for (int i = tid; i < 612 * 4; i += 1024) {
        int px = i >> 2, j = i & 3;
        int yy = px / 34, xx = px - yy * 34;
        int gy = y0 - 1 + yy, gx = x0 - 1 + xx;
        uint4 v = {0u, 0u, 0u, 0u};
        if ((unsigned)gy < HGT && (unsigned)gx < WID)
            v = *(const uint4*)(inb + (size_t)(gy * WID + gx) * 32 + j * 8);
        *(uint4*)(s_act + px * AS + j * 8) = v;
    }
    for (int i = tid; i < 2304; i += 1024)
        ((uint4*)s_wb)[i] = ((const uint4*)wp)[i];
    __syncthreads();

    const int warp = tid >> 5, lane = tid & 31;
    const int row = warp >> 1, nh = warp & 1;
    const int qid = lane >> 2, tig = lane & 3;

    float acc[2][4][4];
    #pragma unroll
    for (int mt = 0; mt < 2; mt++)
        #pragma unroll
        for (int nt = 0; nt < 4; nt++)
            #pragma unroll
            for (int u = 0; u < 4; u++) acc[mt][nt][u] = 0.f;

    #pragma unroll 1
    for (int tap = 0; tap < 9; tap++) {
        const int pxb = (row + tap / 3) * 34 + tap % 3 + qid;
        #pragma unroll
        for (int kk = 0; kk < 2; kk++) {
            uint32_t a[2][4];
            #pragma unroll
            for (int mt = 0; mt < 2; mt++) {
                const __half* ap = s_act + (pxb + mt * 16) * AS + kk * 16 + 2 * tig;
                a[mt][0] = *(const uint32_t*)(ap);
                a[mt][1] = *(const uint32_t*)(ap + 8 * AS);
                a[mt][2] = *(const uint32_t*)(ap + 8);
                a[mt][3] = *(const uint32_t*)(ap + 8 * AS + 8);
            }
            const char* wb = s_wb + ((tap * 2 + kk) * 2 + nh) * 1024 + lane * 16;
            uint4 B0 = *(const uint4*)wb;
            uint4 B1 = *(const uint4*)(wb + 512);
            #pragma unroll
            for (int mt = 0; mt < 2; mt++) {
                MMA_F16(acc[mt][0], a[mt], B0.x, B0.y);
                MMA_F16(acc[mt][1], a[mt], B0.z, B0.w);
                MMA_F16(acc[mt][2], a[mt], B1.x, B1.y);
                MMA_F16(acc[mt][3], a[mt], B1.z, B1.w);
            }
        }
    }

    __half* ob = outp + ((size_t)b * HW + (size_t)(y0 + row) * WID + x0) * 64;
    #pragma unroll
    for (int nt = 0; nt < 4; nt++) {
        int n = nh * 32 + nt * 8 + 2 * tig;
        float bv0 = __ldg(bias + n), bv1 = __ldg(bias + n + 1);
        #pragma unroll
        for (int mt = 0; mt < 2; mt++)
            #pragma unroll
            for (int hh = 0; hh < 2; hh++) {
                int x = qid + mt * 16 + hh * 8;
                float v0 = fmaxf(acc[mt][nt][hh * 2 + 0] + bv0, 0.f);
                float v1 = fmaxf(acc[mt][nt][hh * 2 + 1] + bv1, 0.f);
                *(__half2*)(ob + (size_t)x * 64 + n) = __floats2half2_rn(v0, v1);
            }
    }
}

// ---------------- conv3: 64->32 fp16 mma k16, 512 thr, 3 CTAs/SM, n-split ----------------
// tile 8x32; 16 warps = 8 rows x 2 nh. N=16/warp (acc 16 regs). cin-halved act.
__global__ void __launch_bounds__(512, 3) conv3_mma(
    const __half* __restrict__ in, const __half* __restrict__ wp,
    const float* __restrict__ bias, __half* __restrict__ outp)
{
    constexpr int AS = 40;
    extern __shared__ char smraw[];
    __half* s_act = (__half*)smraw;          // 10*34*40*2 = 27200 B
    char*   s_wb  = smraw + 27200;           // 9216*2 = 18432 B

    const int tid = threadIdx.x;
    const int b   = blockIdx.z;
    const int x0  = blockIdx.x * 32;
    const int y0  = blockIdx.y * 8;

    const __half* inb = in + (size_t)b * HW * 64;
    const int warp = tid >> 5, lane = tid & 31;
    const int row = warp >> 1, nh = warp & 1;
    const int qid = lane >> 2, tig = lane & 3;

    float acc[2][2][4];
    #pragma unroll
    for (int mt = 0; mt < 2; mt++)
        #pragma unroll
        for (int nt = 0; nt < 2; nt++)
            #pragma unroll
            for (int u = 0; u < 4; u++) acc[mt][nt][u] = 0.f;

    #pragma unroll 1
    for (int h = 0; h < 2; h++) {
        if (h) __syncthreads();
        for (int i = tid; i < 340 * 4; i += 512) {
            int px = i >> 2, j = i & 3;
            int yy = px / 34, xx = px - yy * 34;
            int gy = y0 - 1 + yy, gx = x0 - 1 + xx;
            uint4 v = {0u, 0u, 0u, 0u};
            if ((unsigned)gy < HGT && (unsigned)gx < WID)
                v = *(const uint4*)(inb + (size_t)(gy * WID + gx) * 64 + h * 32 + j * 8);
            *(uint4*)(s_act + px * AS + j * 8) = v;
        }
        for (int i = tid; i < 1152; i += 512)
            ((uint4*)s_wb)[i] = ((const uint4*)(wp + (size_t)h * 9216))[i];
        __syncthreads();

        #pragma unroll 1
        for (int tap = 0; tap < 9; tap++) {
            const int pxb = (row + tap / 3) * 34 + tap % 3 + qid;
            #pragma unroll
            for (int kk = 0; kk < 2; kk++) {
                uint32_t a[2][4];
                #pragma unroll
                for (int mt = 0; mt < 2; mt++) {
                    const __half* ap = s_act + (pxb + mt * 16) * AS + kk * 16 + 2 * tig;
                    a[mt][0] = *(const uint32_t*)(ap);
                    a[mt][1] = *(const uint32_t*)(ap + 8 * AS);
                    a[mt][2] = *(const uint32_t*)(ap + 8);
                    a[mt][3] = *(const uint32_t*)(ap + 8 * AS + 8);
                }
                const char* wb = s_wb + ((tap * 2 + kk) * 2 + nh) * 512 + lane * 16;
                uint4 B0 = *(const uint4*)wb;
                #pragma unroll
                for (int mt = 0; mt < 2; mt++) {
                    MMA_F16(acc[mt][0], a[mt], B0.x, B0.y);
                    MMA_F16(acc[mt][1], a[mt], B0.z, B0.w);
                }
            }
        }
    }

    __half* ob = outp + ((size_t)b * HW + (size_t)(y0 + row) * WID + x0) * 32;
    #pragma unroll
    for (int nt = 0; nt < 2; nt++) {
        int n = nh * 16 + nt * 8 + 2 * tig;
        float bv0 = __ldg(bias + n), bv1 = __ldg(bias + n + 1);
        #pragma unroll
        for (int mt = 0; mt < 2; mt++)
            #pragma unroll
            for (int hh = 0; hh < 2; hh++) {
                int x = qid + mt * 16 + hh * 8;
                float v0 = fmaxf(acc[mt][nt][hh * 2 + 0] + bv0, 0.f);
                float v1 = fmaxf(acc[mt][nt][hh * 2 + 1] + bv1, 0.f);
                *(__half2*)(ob + (size_t)x * 32 + n) = __floats2half2_rn(v0, v1);
            }
    }
}

// ---------------- conv4: 32->1 fp32 fused final (half in) ----------------
__global__ void __launch_bounds__(256, 1) conv4_k(
    const __half* __restrict__ a3, const float* __restrict__ w4,
    const float* __restrict__ b4, const float* __restrict__ sf,
    float* __restrict__ out)
{
    extern __shared__ float sm[];
    float* s_act = sm;                 // 18x18 px * 36
    float* s_w   = sm + 324 * 36;
    const int tid = threadIdx.x;
    const int b = blockIdx.z, x0 = blockIdx.x * 16, y0 = blockIdx.y * 16;

    const __half* inb = a3 + (size_t)b * HW * 32;
    for (int i = tid; i < 324 * 4; i += 256) {
        int px = i >> 2, j = i & 3;
        int yy = px / 18, xx = px - yy * 18;
        int gy = y0 - 1 + yy, gx = x0 - 1 + xx;
        float2 f[4] = {{0.f,0.f},{0.f,0.f},{0.f,0.f},{0.f,0.f}};
        if ((unsigned)gy < HGT && (unsigned)gx < WID) {
            uint4 v = *(const uint4*)(inb + (size_t)(gy * WID + gx) * 32 + j * 8);
            f[0] = __half22float2(*(__half2*)&v.x);
            f[1] = __half22float2(*(__half2*)&v.y);
            f[2] = __half22float2(*(__half2*)&v.z);
            f[3] = __half22float2(*(__half2*)&v.w);
        }
        float* sp = s_act + px * 36 + j * 8;
        sp[0] = f[0].x; sp[1] = f[0].y; sp[2] = f[1].x; sp[3] = f[1].y;
        sp[4] = f[2].x; sp[5] = f[2].y; sp[6] = f[3].x; sp[7] = f[3].y;
    }
    for (int i = tid; i < 288; i += 256) s_w[(i % 9) * 32 + i / 9] = w4[i];
    __syncthreads();

    const int py = tid >> 4, px = tid & 15;
    float acc = 0.f;
    #pragma unroll
    for (int t = 0; t < 9; t++) {
        const float* sp = s_act + ((py + t / 3) * 18 + px + t % 3) * 36;
        const float* wpt = s_w + t * 32;
        #pragma unroll
        for (int c4 = 0; c4 < 8; c4++) {
            float4 xv = *(const float4*)(sp + c4 * 4);
            float4 wv = *(const float4*)(wpt + c4 * 4);
            acc = fmaf(xv.x, wv.x, acc);
            acc = fmaf(xv.y, wv.y, acc);
            acc = fmaf(xv.z, wv.z, acc);
            acc = fmaf(xv.w, wv.w, acc);
        }
    }
    float vh = (acc + b4[0]) * sf[0];
    size_t idx = (size_t)b * HW + (size_t)(y0 + py) * WID + (x0 + px);
    out[5 * (size_t)BHW + idx] = vh;
    out[idx] = out[(size_t)BHW + idx] + vh;
}

// ---------------- launch ----------------
extern "C" void kernel_launch(void* const* d_in, const int* in_sizes, int n_in,
                              void* d_out, int out_size)
{
    const float* inputs = (const float*)d_in[0];
    const float* H0     = (const float*)d_in[1];
    const float* C0     = (const float*)d_in[2];
    const float* c2     = (const float*)d_in[3];
    const float* sf     = (const float*)d_in[4];
    const float* w1     = (const float*)d_in[5];
    const float* b1     = (const float*)d_in[6];
    const float* w2     = (const float*)d_in[7];
    const float* b2     = (const float*)d_in[8];
    const float* w3     = (const float*)d_in[9];
    const float* b3     = (const float*)d_in[10];
    const float* w4     = (const float*)d_in[11];
    const float* b4     = (const float*)d_in[12];
    float* out = (float*)d_out;

    __half *actAh, *actBh, *actCh, *w2p, *w3p;
    cudaGetSymbolAddress((void**)&actAh, g_actAh);
    cudaGetSymbolAddress((void**)&actBh, g_actBh);
    cudaGetSymbolAddress((void**)&actCh, g_actCh);
    cudaGetSymbolAddress((void**)&w2p,   g_w2p);
    cudaGetSymbolAddress((void**)&w3p,   g_w3p);

    const int SM2 = 48960 + 36864;         // 85824, 1 CTA/SM
    const int SM3 = 27200 + 18432;         // 45632 -> 3 CTAs/SM
    const int SM4 = (324 * 36 + 288) * 4;  // 47808

    cudaFuncSetAttribute(conv2_mma, cudaFuncAttributeMaxDynamicSharedMemorySize, SM2);
    cudaFuncSetAttribute(conv3_mma, cudaFuncAttributeMaxDynamicSharedMemorySize, SM3);
    cudaFuncSetAttribute(conv4_k,   cudaFuncAttributeMaxDynamicSharedMemorySize, SM4);

    w_pack_k<<<144, 256>>>(w2, w3, w2p, w3p);

    dim3 pg(WID / 16, HGT / 16, BATCH);   // (16, 16, 8)
    fuse_pc1_k<<<pg, 256>>>(inputs, H0, C0, c2, sf, w1, b1, out, actAh);

    dim3 tcg2(WID / 32, HGT / 16, BATCH); // (8, 16, 8)
    conv2_mma<<<tcg2, 1024, SM2>>>(actAh, w2p, b2, actBh);

    dim3 tcg3(WID / 32, HGT / 8, BATCH);  // (8, 32, 8)
    conv3_mma<<<tcg3, 512, SM3>>>(actBh, w3p, b3, actCh);

    conv4_k<<<pg, 256, SM4>>>(actCh, w4, b4, sf, out);
}

// round 15
// speedup vs baseline: 1.1748x; 1.1748x over previous
#include <cuda_runtime.h>
#include <cuda_fp16.h>
#include <cstdint>

#define WID 256
#define HGT 256
#define HW  65536
#define BATCH 8
#define BHW 524288

// ---------------- scratch ----------------
__device__ __half g_actAh[(size_t)BATCH * HW * 32];  // conv1 out (half, NHWC)
__device__ __half g_actBh[(size_t)BATCH * HW * 64];  // conv2 out (half, NHWC)
__device__ __half g_actCh[(size_t)BATCH * HW * 32];  // conv3 out (half, NHWC)
__device__ __half g_w1p[512];                        // conv1 w packed, 1KB block
__device__ __half g_w2p[9 * 2 * 2 * 512];            // conv2 w packed (tap,kk,nh) 1KB blocks
__device__ __half g_w3p[2 * 9 * 2 * 2 * 512];        // conv3 w packed (h,tap,kk) 1KB blocks

// ---------------- helpers ----------------
#define MMA_F16(d, a, b0, b1) \
    asm volatile("mma.sync.aligned.m16n8k16.row.col.f32.f16.f16.f32 " \
        "{%0,%1,%2,%3}, {%4,%5,%6,%7}, {%8,%9}, {%0,%1,%2,%3};" \
        : "+f"((d)[0]), "+f"((d)[1]), "+f"((d)[2]), "+f"((d)[3]) \
        : "r"((a)[0]), "r"((a)[1]), "r"((a)[2]), "r"((a)[3]), "r"(b0), "r"(b1))

// ---------------- weight pack: fp16, exact fragment order ----------------
__global__ void __launch_bounds__(256) w_pack_k(
    const float* __restrict__ w1, const float* __restrict__ w2,
    const float* __restrict__ w3, __half* __restrict__ p1,
    __half* __restrict__ p2, __half* __restrict__ p3)
{
    int idx = blockIdx.x * 256 + threadIdx.x;   // < 36864
    if (idx < 512) {     // conv1: single kk block, K=16 (9 taps + pad)
        int e = idx & 7, lane = (idx >> 3) & 31, blk = (idx >> 8) & 1;
        int qid = lane >> 2, tig = lane & 3;
        int nt = blk * 2 + (e >> 2), breg = (e >> 1) & 1, lo = e & 1;
        int k = breg * 8 + 2 * tig + lo;
        int n = nt * 8 + qid;
        p1[(blk * 32 + lane) * 8 + e] =
            (k < 9) ? __float2half_rn(w1[n * 9 + k]) : __half(0.f);
    }
    if (idx < 18432) {   // conv2: nh-split (N=32 per warp), 1KB blocks
        int e = idx & 7, lane = (idx >> 3) & 31;
        int blk = (idx >> 8) & 1, nh = (idx >> 9) & 1;
        int kk = (idx >> 10) & 1, tap = idx >> 11;
        int qid = lane >> 2, tig = lane & 3;
        int nt = blk * 2 + (e >> 2), breg = (e >> 1) & 1, lo = e & 1;
        int k = kk * 16 + breg * 8 + 2 * tig + lo;
        int n = nh * 32 + nt * 8 + qid;
        p2[((((tap * 2 + kk) * 2 + nh) * 2 + blk) * 32 + lane) * 8 + e] =
            __float2half_rn(w2[((size_t)n * 32 + k) * 9 + tap]);
    }
    {   // conv3: full-n (R13), cin-half h, 1KB blocks
        int h = idx / 18432, r = idx - h * 18432;
        int tap = r / 2048, r2 = r - tap * 2048;
        int kk = (r2 >> 10) & 1, blk = (r2 >> 9) & 1;
        int lane = (r2 >> 3) & 31, e = r2 & 7;
        int qid = lane >> 2, tig = lane & 3;
        int nt = blk * 2 + (e >> 2), breg = (e >> 1) & 1, lo = e & 1;
        int k = h * 32 + kk * 16 + breg * 8 + 2 * tig + lo;
        int n = nt * 8 + qid;
        p3[(size_t)h * 18432 +
           (((tap * 2 + kk) * 2 + blk) * 32 + lane) * 8 + e] =
            __float2half_rn(w3[((size_t)n * 64 + k) * 9 + tap]);
    }
}

// ---------------- fused prep + conv1 (mma) ----------------
// 16x16 px tile: elementwise (H,V,C_new) fp32 + conv1 as m16n8k16 mma (K=16 im2col).
__global__ void __launch_bounds__(256) fuse_pc1_k(
    const float* __restrict__ inp, const float* __restrict__ H0,
    const float* __restrict__ C0, const float* __restrict__ c2,
    const float* __restrict__ sf, const __half* __restrict__ w1p,
    const float* __restrict__ b1, float* __restrict__ out,
    __half* __restrict__ actA)
{
    __shared__ float  s_in[324];
    __shared__ float  s_vs[324];
    __shared__ __half s_a[256 * 20];   // im2col, stride 20 halves
    __shared__ __half s_w1[512];
    __shared__ float  sb[32];

    const int tid = threadIdx.x;
    const int b = blockIdx.z, x0 = blockIdx.x * 16, y0 = blockIdx.y * 16;

    if (tid < 32) sb[tid] = b1[tid];
    if (tid < 64) ((uint4*)s_w1)[tid] = ((const uint4*)w1p)[tid];
    const float sfv = sf[0];

    for (int i = tid; i < 324; i += 256) {
        int yy = i / 18, xx = i - yy * 18;
        int gy = y0 - 1 + yy, gx = x0 - 1 + xx;
        float iv = 0.f, vsv = 0.f;
        if ((unsigned)gy < HGT && (unsigned)gx < WID) {
            int gidx = (b << 16) + (gy << 8) + gx;
            iv  = inp[gidx];
            vsv = (iv - H0[gidx]) / sfv;
        }
        s_in[i] = iv;
        s_vs[i] = vsv;
    }
    __syncthreads();

    const int py = tid >> 4, px = tid & 15;
    const int si = (py + 1) * 18 + px + 1;
    const int rem = ((y0 + py) << 8) + x0 + px;
    const int idx = (b << 16) + rem;

    float cc  = s_in[si];
    float lap = s_in[si - 18] + s_in[si + 18] + s_in[si - 1] + s_in[si + 1] - 4.f * cc;
    float c0v = C0[(size_t)b * 2 * HW + rem];
    float Hv  = 2.f * cc - c0v + c2[0] * lap;
    float V   = cc - H0[idx];

    out[(size_t)BHW + idx]     = Hv;
    out[4 * (size_t)BHW + idx] = V;
    out[2 * (size_t)BHW + (size_t)b * 2 * HW + rem]      = cc;
    out[2 * (size_t)BHW + (size_t)b * 2 * HW + HW + rem] = c0v;

    // im2col row for this pixel: 9 taps + 7 zeros
    {
        __half* ap = s_a + tid * 20;
        #pragma unroll
        for (int t = 0; t < 9; t++)
            ap[t] = __float2half_rn(s_vs[(py + t / 3) * 18 + px + t % 3]);
        #pragma unroll
        for (int t = 9; t < 16; t++) ap[t] = __half(0.f);
    }
    __syncthreads();

    // conv1 mma: warp w -> pixels [w*32, w*32+32), M=32, N=32, K=16
    const int warp = tid >> 5, lane = tid & 31;
    const int qid = lane >> 2, tig = lane & 3;

    float acc[2][4][4];
    #pragma unroll
    for (int mt = 0; mt < 2; mt++)
        #pragma unroll
        for (int nt = 0; nt < 4; nt++)
            #pragma unroll
            for (int u = 0; u < 4; u++) acc[mt][nt][u] = 0.f;

    uint32_t a[2][4];
    #pragma unroll
    for (int mt = 0; mt < 2; mt++) {
        const __half* ap = s_a + (warp * 32 + mt * 16 + qid) * 20 + 2 * tig;
        a[mt][0] = *(const uint32_t*)(ap);
        a[mt][1] = *(const uint32_t*)(ap + 8 * 20);
        a[mt][2] = *(const uint32_t*)(ap + 8);
        a[mt][3] = *(const uint32_t*)(ap + 8 * 20 + 8);
    }
    {
        const char* wb = (const char*)s_w1 + lane * 16;
        uint4 B0 = *(const uint4*)wb;
        uint4 B1 = *(const uint4*)(wb + 512);
        #pragma unroll
        for (int mt = 0; mt < 2; mt++) {
            MMA_F16(acc[mt][0], a[mt], B0.x, B0.y);
            MMA_F16(acc[mt][1], a[mt], B0.z, B0.w);
            MMA_F16(acc[mt][2], a[mt], B1.x, B1.y);
            MMA_F16(acc[mt][3], a[mt], B1.z, B1.w);
        }
    }

    // epilogue: bias + relu, half2 NHWC stores
    #pragma unroll
    for (int nt = 0; nt < 4; nt++) {
        int n = nt * 8 + 2 * tig;
        float bv0 = sb[n], bv1 = sb[n + 1];
        #pragma unroll
        for (int mt = 0; mt < 2; mt++)
            #pragma unroll
            for (int hh = 0; hh < 2; hh++) {
                int p = warp * 32 + mt * 16 + hh * 8 + qid;
                int gpx = ((b << 16) + ((y0 + (p >> 4)) << 8) + x0 + (p & 15));
                float v0 = fmaxf(acc[mt][nt][hh * 2 + 0] + bv0, 0.f);
                float v1 = fmaxf(acc[mt][nt][hh * 2 + 1] + bv1, 0.f);
                *(__half2*)(actA + (size_t)gpx * 32 + n) = __floats2half2_rn(v0, v1);
            }
    }
}

// ---------------- conv2: 32->64 fp16 mma k16, 1024 thr, n-split (R13, proven) ----------------
__global__ void __launch_bounds__(1024, 1) conv2_mma(
    const __half* __restrict__ in, const __half* __restrict__ wp,
    const float* __restrict__ bias, __half* __restrict__ outp)
{
    constexpr int AS = 40;
    extern __shared__ char smraw[];
    __half* s_act = (__half*)smraw;          // 48960 B
    char*   s_wb  = smraw + 48960;           // 36864 B

    const int tid = threadIdx.x;
    const int b   = blockIdx.z;
    const int x0  = blockIdx.x * 32;
    const int y0  = blockIdx.y * 16;

    const __half* inb = in + (size_t)b * HW * 32;
    for (int i = tid; i < 612 * 4; i += 1024) {
        int px = i >> 2, j = i & 3;
        int yy = px / 34, xx = px - yy * 34;
        int gy = y0 - 1 + yy, gx = x0 - 1 + xx;
        uint4 v = {0u, 0u, 0u, 0u};
        if ((unsigned)gy < HGT && (unsigned)gx < WID)
            v = *(const uint4*)(inb + (size_t)(gy * WID + gx) * 32 + j * 8);
        *(uint4*)(s_act + px * AS + j * 8) = v;
    }
    for (int i = tid; i < 2304; i += 1024)
        ((uint4*)s_wb)[i] = ((const uint4*)wp)[i];
    __syncthreads();

    const int warp = tid >> 5, lane = tid & 31;
    const int row = warp >> 1, nh = warp & 1;
    const int qid = lane >> 2, tig = lane & 3;

    float acc[2][4][4];
    #pragma unroll
    for (int mt = 0; mt < 2; mt++)
        #pragma unroll
        for (int nt = 0; nt < 4; nt++)
            #pragma unroll
            for (int u = 0; u < 4; u++) acc[mt][nt][u] = 0.f;

    #pragma unroll 1
    for (int tap = 0; tap < 9; tap++) {
        const int pxb = (row + tap / 3) * 34 + tap % 3 + qid;
        #pragma unroll
        for (int kk = 0; kk < 2; kk++) {
            uint32_t a[2][4];
            #pragma unroll
            for (int mt = 0; mt < 2; mt++) {
                const __half* ap = s_act + (pxb + mt * 16) * AS + kk * 16 + 2 * tig;
                a[mt][0] = *(const uint32_t*)(ap);
                a[mt][1] = *(const uint32_t*)(ap + 8 * AS);
                a[mt][2] = *(const uint32_t*)(ap + 8);
                a[mt][3] = *(const uint32_t*)(ap + 8 * AS + 8);
            }
            const char* wb = s_wb + ((tap * 2 + kk) * 2 + nh) * 1024 + lane * 16;
            uint4 B0 = *(const uint4*)wb;
            uint4 B1 = *(const uint4*)(wb + 512);
            #pragma unroll
            for (int mt = 0; mt < 2; mt++) {
                MMA_F16(acc[mt][0], a[mt], B0.x, B0.y);
                MMA_F16(acc[mt][1], a[mt], B0.z, B0.w);
                MMA_F16(acc[mt][2], a[mt], B1.x, B1.y);
                MMA_F16(acc[mt][3], a[mt], B1.z, B1.w);
            }
        }
    }

    __half* ob = outp + ((size_t)b * HW + (size_t)(y0 + row) * WID + x0) * 64;
    #pragma unroll
    for (int nt = 0; nt < 4; nt++) {
        int n = nh * 32 + nt * 8 + 2 * tig;
        float bv0 = __ldg(bias + n), bv1 = __ldg(bias + n + 1);
        #pragma unroll
        for (int mt = 0; mt < 2; mt++)
            #pragma unroll
            for (int hh = 0; hh < 2; hh++) {
                int x = qid + mt * 16 + hh * 8;
                float v0 = fmaxf(acc[mt][nt][hh * 2 + 0] + bv0, 0.f);
                float v1 = fmaxf(acc[mt][nt][hh * 2 + 1] + bv1, 0.f);
                *(__half2*)(ob + (size_t)x * 64 + n) = __floats2half2_rn(v0, v1);
            }
    }
}

// ---------------- conv3: R13 config (full-n, 512 thr, 2 CTAs/SM), half out ----------------
__global__ void __launch_bounds__(512, 2) conv3_mma(
    const __half* __restrict__ in, const __half* __restrict__ wp,
    const float* __restrict__ bias, __half* __restrict__ outp)
{
    constexpr int AS = 40;
    extern __shared__ char smraw[];
    __half* s_act = (__half*)smraw;          // 48960 B
    char*   s_wb  = smraw + 48960;           // 18432 B

    const int tid = threadIdx.x;
    const int b   = blockIdx.z;
    const int x0  = blockIdx.x * 32;
    const int y0  = blockIdx.y * 16;

    const __half* inb = in + (size_t)b * HW * 64;
    const int warp = tid >> 5, lane = tid & 31;
    const int qid = lane >> 2, tig = lane & 3;

    float acc[2][4][4];
    #pragma unroll
    for (int mt = 0; mt < 2; mt++)
        #pragma unroll
        for (int nt = 0; nt < 4; nt++)
            #pragma unroll
            for (int u = 0; u < 4; u++) acc[mt][nt][u] = 0.f;

    #pragma unroll 1
    for (int h = 0; h < 2; h++) {
        if (h) __syncthreads();
        for (int i = tid; i < 612 * 4; i += 512) {
            int px = i >> 2, j = i & 3;
            int yy = px / 34, xx = px - yy * 34;
            int gy = y0 - 1 + yy, gx = x0 - 1 + xx;
            uint4 v = {0u, 0u, 0u, 0u};
            if ((unsigned)gy < HGT && (unsigned)gx < WID)
                v = *(const uint4*)(inb + (size_t)(gy * WID + gx) * 64 + h * 32 + j * 8);
            *(uint4*)(s_act + px * AS + j * 8) = v;
        }
        for (int i = tid; i < 1152; i += 512)
            ((uint4*)s_wb)[i] = ((const uint4*)(wp + (size_t)h * 18432))[i];
        __syncthreads();

        #pragma unroll 1
        for (int tap = 0; tap < 9; tap++) {
            const int pxb = (warp + tap / 3) * 34 + tap % 3 + qid;
            #pragma unroll
            for (int kk = 0; kk < 2; kk++) {
                uint32_t a[2][4];
                #pragma unroll
                for (int mt = 0; mt < 2; mt++) {
                    const __half* ap = s_act + (pxb + mt * 16) * AS + kk * 16 + 2 * tig;
                    a[mt][0] = *(const uint32_t*)(ap);
                    a[mt][1] = *(const uint32_t*)(ap + 8 * AS);
                    a[mt][2] = *(const uint32_t*)(ap + 8);
                    a[mt][3] = *(const uint32_t*)(ap + 8 * AS + 8);
                }
                const char* wb = s_wb + (tap * 2 + kk) * 1024 + lane * 16;
                uint4 B0 = *(const uint4*)wb;
                uint4 B1 = *(const uint4*)(wb + 512);
                #pragma unroll
                for (int mt = 0; mt < 2; mt++) {
                    MMA_F16(acc[mt][0], a[mt], B0.x, B0.y);
                    MMA_F16(acc[mt][1], a[mt], B0.z, B0.w);
                    MMA_F16(acc[mt][2], a[mt], B1.x, B1.y);
                    MMA_F16(acc[mt][3], a[mt], B1.z, B1.w);
                }
            }
        }
    }

    __half* ob = outp + ((size_t)b * HW + (size_t)(y0 + warp) * WID + x0) * 32;
    #pragma unroll
    for (int nt = 0; nt < 4; nt++) {
        int n = nt * 8 + 2 * tig;
        float bv0 = __ldg(bias + n), bv1 = __ldg(bias + n + 1);
        #pragma unroll
        for (int mt = 0; mt < 2; mt++)
            #pragma unroll
            for (int hh = 0; hh < 2; hh++) {
                int x = qid + mt * 16 + hh * 8;
                float v0 = fmaxf(acc[mt][nt][hh * 2 + 0] + bv0, 0.f);
                float v1 = fmaxf(acc[mt][nt][hh * 2 + 1] + bv1, 0.f);
                *(__half2*)(ob + (size_t)x * 32 + n) = __floats2half2_rn(v0, v1);
            }
    }
}

// ---------------- conv4: 32->1 fp32 fused final (half in, R14) ----------------
__global__ void __launch_bounds__(256, 1) conv4_k(
    const __half* __restrict__ a3, const float* __restrict__ w4,
    const float* __restrict__ b4, const float* __restrict__ sf,
    float* __restrict__ out)
{
    extern __shared__ float sm[];
    float* s_act = sm;                 // 18x18 px * 36
    float* s_w   = sm + 324 * 36;
    const int tid = threadIdx.x;
    const int b = blockIdx.z, x0 = blockIdx.x * 16, y0 = blockIdx.y * 16;

    const __half* inb = a3 + (size_t)b * HW * 32;
    for (int i = tid; i < 324 * 4; i += 256) {
        int px = i >> 2, j = i & 3;
        int yy = px / 18, xx = px - yy * 18;
        int gy = y0 - 1 + yy, gx = x0 - 1 + xx;
        float2 f[4] = {{0.f,0.f},{0.f,0.f},{0.f,0.f},{0.f,0.f}};
        if ((unsigned)gy < HGT && (unsigned)gx < WID) {
            uint4 v = *(const uint4*)(inb + (size_t)(gy * WID + gx) * 32 + j * 8);
            f[0] = __half22float2(*(__half2*)&v.x);
            f[1] = __half22float2(*(__half2*)&v.y);
            f[2] = __half22float2(*(__half2*)&v.z);
            f[3] = __half22float2(*(__half2*)&v.w);
        }
        float* sp = s_act + px * 36 + j * 8;
        sp[0] = f[0].x; sp[1] = f[0].y; sp[2] = f[1].x; sp[3] = f[1].y;
        sp[4] = f[2].x; sp[5] = f[2].y; sp[6] = f[3].x; sp[7] = f[3].y;
    }
    for (int i = tid; i < 288; i += 256) s_w[(i % 9) * 32 + i / 9] = w4[i];
    __syncthreads();

    const int py = tid >> 4, px = tid & 15;
    float acc = 0.f;
    #pragma unroll
    for (int t = 0; t < 9; t++) {
        const float* sp = s_act + ((py + t / 3) * 18 + px + t % 3) * 36;
        const float* wpt = s_w + t * 32;
        #pragma unroll
        for (int c4 = 0; c4 < 8; c4++) {
            float4 xv = *(const float4*)(sp + c4 * 4);
            float4 wv = *(const float4*)(wpt + c4 * 4);
            acc = fmaf(xv.x, wv.x, acc);
            acc = fmaf(xv.y, wv.y, acc);
            acc = fmaf(xv.z, wv.z, acc);
            acc = fmaf(xv.w, wv.w, acc);
        }
    }
    float vh = (acc + b4[0]) * sf[0];
    size_t idx = (size_t)b * HW + (size_t)(y0 + py) * WID + (x0 + px);
    out[5 * (size_t)BHW + idx] = vh;
    out[idx] = out[(size_t)BHW + idx] + vh;
}

// ---------------- launch ----------------
extern "C" void kernel_launch(void* const* d_in, const int* in_sizes, int n_in,
                              void* d_out, int out_size)
{
    const float* inputs = (const float*)d_in[0];
    const float* H0     = (const float*)d_in[1];
    const float* C0     = (const float*)d_in[2];
    const float* c2     = (const float*)d_in[3];
    const float* sf     = (const float*)d_in[4];
    const float* w1     = (const float*)d_in[5];
    const float* b1     = (const float*)d_in[6];
    const float* w2     = (const float*)d_in[7];
    const float* b2     = (const float*)d_in[8];
    const float* w3     = (const float*)d_in[9];
    const float* b3     = (const float*)d_in[10];
    const float* w4     = (const float*)d_in[11];
    const float* b4     = (const float*)d_in[12];
    float* out = (float*)d_out;

    __half *actAh, *actBh, *actCh, *w1p, *w2p, *w3p;
    cudaGetSymbolAddress((void**)&actAh, g_actAh);
    cudaGetSymbolAddress((void**)&actBh, g_actBh);
    cudaGetSymbolAddress((void**)&actCh, g_actCh);
    cudaGetSymbolAddress((void**)&w1p,   g_w1p);
    cudaGetSymbolAddress((void**)&w2p,   g_w2p);
    cudaGetSymbolAddress((void**)&w3p,   g_w3p);

    const int SM2 = 48960 + 36864;         // 85824, 1 CTA/SM
    const int SM3 = 48960 + 18432;         // 67392 -> 2 CTAs/SM
    const int SM4 = (324 * 36 + 288) * 4;  // 47808

    cudaFuncSetAttribute(conv2_mma, cudaFuncAttributeMaxDynamicSharedMemorySize, SM2);
    cudaFuncSetAttribute(conv3_mma, cudaFuncAttributeMaxDynamicSharedMemorySize, SM3);
    cudaFuncSetAttribute(conv4_k,   cudaFuncAttributeMaxDynamicSharedMemorySize, SM4);

    w_pack_k<<<144, 256>>>(w1, w2, w3, w1p, w2p, w3p);

    dim3 pg(WID / 16, HGT / 16, BATCH);   // (16, 16, 8)
    fuse_pc1_k<<<pg, 256>>>(inputs, H0, C0, c2, sf, w1p, b1, out, actAh);

    dim3 tcg2(WID / 32, HGT / 16, BATCH); // (8, 16, 8)
    conv2_mma<<<tcg2, 1024, SM2>>>(actAh, w2p, b2, actBh);
    conv3_mma<<<tcg2,  512, SM3>>>(actBh, w3p, b3, actCh);

    conv4_k<<<pg, 256, SM4>>>(actCh, w4, b4, sf, out);
}

// round 16
// speedup vs baseline: 1.2455x; 1.0602x over previous
#include <cuda_runtime.h>
#include <cuda_fp16.h>
#include <cstdint>

#define WID 256
#define HGT 256
#define HW  65536
#define BATCH 8
#define BHW 524288

// ---------------- scratch ----------------
__device__ __half g_actAh[(size_t)BATCH * HW * 32];  // conv1 out (half, NHWC)
__device__ __half g_actBh[(size_t)BATCH * HW * 64];  // conv2 out (half, NHWC)
__device__ __half g_actCh[(size_t)BATCH * HW * 32];  // conv3 out (half, NHWC)
__device__ __half g_w1p[512];                        // conv1 w packed, 1KB block
__device__ __half g_w2p[9 * 2 * 2 * 512];            // conv2 w packed (tap,kk,nh) 1KB blocks
__device__ __half g_w3p[2 * 9 * 2 * 2 * 512];        // conv3 w packed (h,tap,kk) 1KB blocks
__device__ __half g_w4p[9 * 2 * 128];                // conv4 w packed (tap,kk) 256B blocks

// ---------------- helpers ----------------
#define MMA_F16(d, a, b0, b1) \
    asm volatile("mma.sync.aligned.m16n8k16.row.col.f32.f16.f16.f32 " \
        "{%0,%1,%2,%3}, {%4,%5,%6,%7}, {%8,%9}, {%0,%1,%2,%3};" \
        : "+f"((d)[0]), "+f"((d)[1]), "+f"((d)[2]), "+f"((d)[3]) \
        : "r"((a)[0]), "r"((a)[1]), "r"((a)[2]), "r"((a)[3]), "r"(b0), "r"(b1))

// ---------------- weight pack: fp16, exact fragment order ----------------
__global__ void __launch_bounds__(256) w_pack_k(
    const float* __restrict__ w1, const float* __restrict__ w2,
    const float* __restrict__ w3, const float* __restrict__ w4,
    __half* __restrict__ p1, __half* __restrict__ p2,
    __half* __restrict__ p3, __half* __restrict__ p4)
{
    int idx = blockIdx.x * 256 + threadIdx.x;   // < 36864
    if (idx < 512) {     // conv1: single kk block, K=16 (9 taps + pad)
        int e = idx & 7, lane = (idx >> 3) & 31, blk = (idx >> 8) & 1;
        int qid = lane >> 2, tig = lane & 3;
        int nt = blk * 2 + (e >> 2), breg = (e >> 1) & 1, lo = e & 1;
        int k = breg * 8 + 2 * tig + lo;
        int n = nt * 8 + qid;
        p1[(blk * 32 + lane) * 8 + e] =
            (k < 9) ? __float2half_rn(w1[n * 9 + k]) : __half(0.f);
    }
    if (idx < 2304) {    // conv4: (tap,kk) 256B blocks, N=8 (only n=0 real)
        int e = idx & 3, lane = (idx >> 2) & 31;
        int kk = (idx >> 7) & 1, tap = idx >> 8;    // tap 0..8
        int qid = lane >> 2, tig = lane & 3;
        int breg = e >> 1, lo = e & 1;
        int k = kk * 16 + breg * 8 + 2 * tig + lo;  // channel 0..31
        p4[((tap * 2 + kk) * 32 + lane) * 4 + e] =
            (qid == 0) ? __float2half_rn(w4[k * 9 + tap]) : __half(0.f);
    }
    if (idx < 18432) {   // conv2: nh-split (N=32 per warp), 1KB blocks
        int e = idx & 7, lane = (idx >> 3) & 31;
        int blk = (idx >> 8) & 1, nh = (idx >> 9) & 1;
        int kk = (idx >> 10) & 1, tap = idx >> 11;
        int qid = lane >> 2, tig = lane & 3;
        int nt = blk * 2 + (e >> 2), breg = (e >> 1) & 1, lo = e & 1;
        int k = kk * 16 + breg * 8 + 2 * tig + lo;
        int n = nh * 32 + nt * 8 + qid;
        p2[((((tap * 2 + kk) * 2 + nh) * 2 + blk) * 32 + lane) * 8 + e] =
            __float2half_rn(w2[((size_t)n * 32 + k) * 9 + tap]);
    }
    {   // conv3: full-n (R13), cin-half h, 1KB blocks
        int h = idx / 18432, r = idx - h * 18432;
        int tap = r / 2048, r2 = r - tap * 2048;
        int kk = (r2 >> 10) & 1, blk = (r2 >> 9) & 1;
        int lane = (r2 >> 3) & 31, e = r2 & 7;
        int qid = lane >> 2, tig = lane & 3;
        int nt = blk * 2 + (e >> 2), breg = (e >> 1) & 1, lo = e & 1;
        int k = h * 32 + kk * 16 + breg * 8 + 2 * tig + lo;
        int n = nt * 8 + qid;
        p3[(size_t)h * 18432 +
           (((tap * 2 + kk) * 2 + blk) * 32 + lane) * 8 + e] =
            __float2half_rn(w3[((size_t)n * 64 + k) * 9 + tap]);
    }
}

// ---------------- fused prep + conv1 (mma, R15 proven) ----------------
__global__ void __launch_bounds__(256) fuse_pc1_k(
    const float* __restrict__ inp, const float* __restrict__ H0,
    const float* __restrict__ C0, const float* __restrict__ c2,
    const float* __restrict__ sf, const __half* __restrict__ w1p,
    const float* __restrict__ b1, float* __restrict__ out,
    __half* __restrict__ actA)
{
    __shared__ float  s_in[324];
    __shared__ float  s_vs[324];
    __shared__ __half s_a[256 * 20];
    __shared__ __half s_w1[512];
    __shared__ float  sb[32];

    const int tid = threadIdx.x;
    const int b = blockIdx.z, x0 = blockIdx.x * 16, y0 = blockIdx.y * 16;

    if (tid < 32) sb[tid] = b1[tid];
    if (tid < 64) ((uint4*)s_w1)[tid] = ((const uint4*)w1p)[tid];
    const float sfv = sf[0];

    for (int i = tid; i < 324; i += 256) {
        int yy = i / 18, xx = i - yy * 18;
        int gy = y0 - 1 + yy, gx = x0 - 1 + xx;
        float iv = 0.f, vsv = 0.f;
        if ((unsigned)gy < HGT && (unsigned)gx < WID) {
            int gidx = (b << 16) + (gy << 8) + gx;
            iv  = inp[gidx];
            vsv = (iv - H0[gidx]) / sfv;
        }
        s_in[i] = iv;
        s_vs[i] = vsv;
    }
    __syncthreads();

    const int py = tid >> 4, px = tid & 15;
    const int si = (py + 1) * 18 + px + 1;
    const int rem = ((y0 + py) << 8) + x0 + px;
    const int idx = (b << 16) + rem;

    float cc  = s_in[si];
    float lap = s_in[si - 18] + s_in[si + 18] + s_in[si - 1] + s_in[si + 1] - 4.f * cc;
    float c0v = C0[(size_t)b * 2 * HW + rem];
    float Hv  = 2.f * cc - c0v + c2[0] * lap;
    float V   = cc - H0[idx];

    out[(size_t)BHW + idx]     = Hv;
    out[4 * (size_t)BHW + idx] = V;
    out[2 * (size_t)BHW + (size_t)b * 2 * HW + rem]      = cc;
    out[2 * (size_t)BHW + (size_t)b * 2 * HW + HW + rem] = c0v;

    {
        __half* ap = s_a + tid * 20;
        #pragma unroll
        for (int t = 0; t < 9; t++)
            ap[t] = __float2half_rn(s_vs[(py + t / 3) * 18 + px + t % 3]);
        #pragma unroll
        for (int t = 9; t < 16; t++) ap[t] = __half(0.f);
    }
    __syncthreads();

    const int warp = tid >> 5, lane = tid & 31;
    const int qid = lane >> 2, tig = lane & 3;

    float acc[2][4][4];
    #pragma unroll
    for (int mt = 0; mt < 2; mt++)
        #pragma unroll
        for (int nt = 0; nt < 4; nt++)
            #pragma unroll
            for (int u = 0; u < 4; u++) acc[mt][nt][u] = 0.f;

    uint32_t a[2][4];
    #pragma unroll
    for (int mt = 0; mt < 2; mt++) {
        const __half* ap = s_a + (warp * 32 + mt * 16 + qid) * 20 + 2 * tig;
        a[mt][0] = *(const uint32_t*)(ap);
        a[mt][1] = *(const uint32_t*)(ap + 8 * 20);
        a[mt][2] = *(const uint32_t*)(ap + 8);
        a[mt][3] = *(const uint32_t*)(ap + 8 * 20 + 8);
    }
    {
        const char* wb = (const char*)s_w1 + lane * 16;
        uint4 B0 = *(const uint4*)wb;
        uint4 B1 = *(const uint4*)(wb + 512);
        #pragma unroll
        for (int mt = 0; mt < 2; mt++) {
            MMA_F16(acc[mt][0], a[mt], B0.x, B0.y);
            MMA_F16(acc[mt][1], a[mt], B0.z, B0.w);
            MMA_F16(acc[mt][2], a[mt], B1.x, B1.y);
            MMA_F16(acc[mt][3], a[mt], B1.z, B1.w);
        }
    }

    #pragma unroll
    for (int nt = 0; nt < 4; nt++) {
        int n = nt * 8 + 2 * tig;
        float bv0 = sb[n], bv1 = sb[n + 1];
        #pragma unroll
        for (int mt = 0; mt < 2; mt++)
            #pragma unroll
            for (int hh = 0; hh < 2; hh++) {
                int p = warp * 32 + mt * 16 + hh * 8 + qid;
                int gpx = ((b << 16) + ((y0 + (p >> 4)) << 8) + x0 + (p & 15));
                float v0 = fmaxf(acc[mt][nt][hh * 2 + 0] + bv0, 0.f);
                float v1 = fmaxf(acc[mt][nt][hh * 2 + 1] + bv1, 0.f);
                *(__half2*)(actA + (size_t)gpx * 32 + n) = __floats2half2_rn(v0, v1);
            }
    }
}

// ---------------- conv2: 32->64 fp16 mma k16, 1024 thr, n-split (R13, proven) ----------------
__global__ void __launch_bounds__(1024, 1) conv2_mma(
    const __half* __restrict__ in, const __half* __restrict__ wp,
    const float* __restrict__ bias, __half* __restrict__ outp)
{
    constexpr int AS = 40;
    extern __shared__ char smraw[];
    __half* s_act = (__half*)smraw;          // 48960 B
    char*   s_wb  = smraw + 48960;           // 36864 B

    const int tid = threadIdx.x;
    const int b   = blockIdx.z;
    const int x0  = blockIdx.x * 32;
    const int y0  = blockIdx.y * 16;

    const __half* inb = in + (size_t)b * HW * 32;
    for (int i = tid; i < 612 * 4; i += 1024) {
        int px = i >> 2, j = i & 3;
        int yy = px / 34, xx = px - yy * 34;
        int gy = y0 - 1 + yy, gx = x0 - 1 + xx;
        uint4 v = {0u, 0u, 0u, 0u};
        if ((unsigned)gy < HGT && (unsigned)gx < WID)
            v = *(const uint4*)(inb + (size_t)(gy * WID + gx) * 32 + j * 8);
        *(uint4*)(s_act + px * AS + j * 8) = v;
    }
    for (int i = tid; i < 2304; i += 1024)
        ((uint4*)s_wb)[i] = ((const uint4*)wp)[i];
    __syncthreads();

    const int warp = tid >> 5, lane = tid & 31;
    const int row = warp >> 1, nh = warp & 1;
    const int qid = lane >> 2, tig = lane & 3;

    float acc[2][4][4];
    #pragma unroll
    for (int mt = 0; mt < 2; mt++)
        #pragma unroll
        for (int nt = 0; nt < 4; nt++)
            #pragma unroll
            for (int u = 0; u < 4; u++) acc[mt][nt][u] = 0.f;

    #pragma unroll 1
    for (int tap = 0; tap < 9; tap++) {
        const int pxb = (row + tap / 3) * 34 + tap % 3 + qid;
        #pragma unroll
        for (int kk = 0; kk < 2; kk++) {
            uint32_t a[2][4];
            #pragma unroll
            for (int mt = 0; mt < 2; mt++) {
                const __half* ap = s_act + (pxb + mt * 16) * AS + kk * 16 + 2 * tig;
                a[mt][0] = *(const uint32_t*)(ap);
                a[mt][1] = *(const uint32_t*)(ap + 8 * AS);
                a[mt][2] = *(const uint32_t*)(ap + 8);
                a[mt][3] = *(const uint32_t*)(ap + 8 * AS + 8);
            }
            const char* wb = s_wb + ((tap * 2 + kk) * 2 + nh) * 1024 + lane * 16;
            uint4 B0 = *(const uint4*)wb;
            uint4 B1 = *(const uint4*)(wb + 512);
            #pragma unroll
            for (int mt = 0; mt < 2; mt++) {
                MMA_F16(acc[mt][0], a[mt], B0.x, B0.y);
                MMA_F16(acc[mt][1], a[mt], B0.z, B0.w);
                MMA_F16(acc[mt][2], a[mt], B1.x, B1.y);
                MMA_F16(acc[mt][3], a[mt], B1.z, B1.w);
            }
        }
    }

    __half* ob = outp + ((size_t)b * HW + (size_t)(y0 + row) * WID + x0) * 64;
    #pragma unroll
    for (int nt = 0; nt < 4; nt++) {
        int n = nh * 32 + nt * 8 + 2 * tig;
        float bv0 = __ldg(bias + n), bv1 = __ldg(bias + n + 1);
        #pragma unroll
        for (int mt = 0; mt < 2; mt++)
            #pragma unroll
            for (int hh = 0; hh < 2; hh++) {
                int x = qid + mt * 16 + hh * 8;
                float v0 = fmaxf(acc[mt][nt][hh * 2 + 0] + bv0, 0.f);
                float v1 = fmaxf(acc[mt][nt][hh * 2 + 1] + bv1, 0.f);
                *(__half2*)(ob + (size_t)x * 64 + n) = __floats2half2_rn(v0, v1);
            }
    }
}

// ---------------- conv3: full-n, 512 thr, 2 CTAs/SM, half out (R15, proven) ----------------
__global__ void __launch_bounds__(512, 2) conv3_mma(
    const __half* __restrict__ in, const __half* __restrict__ wp,
    const float* __restrict__ bias, __half* __restrict__ outp)
{
    constexpr int AS = 40;
    extern __shared__ char smraw[];
    __half* s_act = (__half*)smraw;          // 48960 B
    char*   s_wb  = smraw + 48960;           // 18432 B

    const int tid = threadIdx.x;
    const int b   = blockIdx.z;
    const int x0  = blockIdx.x * 32;
    const int y0  = blockIdx.y * 16;

    const __half* inb = in + (size_t)b * HW * 64;
    const int warp = tid >> 5, lane = tid & 31;
    const int qid = lane >> 2, tig = lane & 3;

    float acc[2][4][4];
    #pragma unroll
    for (int mt = 0; mt < 2; mt++)
        #pragma unroll
        for (int nt = 0; nt < 4; nt++)
            #pragma unroll
            for (int u = 0; u < 4; u++) acc[mt][nt][u] = 0.f;

    #pragma unroll 1
    for (int h = 0; h < 2; h++) {
        if (h) __syncthreads();
        for (int i = tid; i < 612 * 4; i += 512) {
            int px = i >> 2, j = i & 3;
            int yy = px / 34, xx = px - yy * 34;
            int gy = y0 - 1 + yy, gx = x0 - 1 + xx;
            uint4 v = {0u, 0u, 0u, 0u};
            if ((unsigned)gy < HGT && (unsigned)gx < WID)
                v = *(const uint4*)(inb + (size_t)(gy * WID + gx) * 64 + h * 32 + j * 8);
            *(uint4*)(s_act + px * AS + j * 8) = v;
        }
        for (int i = tid; i < 1152; i += 512)
            ((uint4*)s_wb)[i] = ((const uint4*)(wp + (size_t)h * 18432))[i];
        __syncthreads();

        #pragma unroll 1
        for (int tap = 0; tap < 9; tap++) {
            const int pxb = (warp + tap / 3) * 34 + tap % 3 + qid;
            #pragma unroll
            for (int kk = 0; kk < 2; kk++) {
                uint32_t a[2][4];
                #pragma unroll
                for (int mt = 0; mt < 2; mt++) {
                    const __half* ap = s_act + (pxb + mt * 16) * AS + kk * 16 + 2 * tig;
                    a[mt][0] = *(const uint32_t*)(ap);
                    a[mt][1] = *(const uint32_t*)(ap + 8 * AS);
                    a[mt][2] = *(const uint32_t*)(ap + 8);
                    a[mt][3] = *(const uint32_t*)(ap + 8 * AS + 8);
                }
                const char* wb = s_wb + (tap * 2 + kk) * 1024 + lane * 16;
                uint4 B0 = *(const uint4*)wb;
                uint4 B1 = *(const uint4*)(wb + 512);
                #pragma unroll
                for (int mt = 0; mt < 2; mt++) {
                    MMA_F16(acc[mt][0], a[mt], B0.x, B0.y);
                    MMA_F16(acc[mt][1], a[mt], B0.z, B0.w);
                    MMA_F16(acc[mt][2], a[mt], B1.x, B1.y);
                    MMA_F16(acc[mt][3], a[mt], B1.z, B1.w);
                }
            }
        }
    }

    __half* ob = outp + ((size_t)b * HW + (size_t)(y0 + warp) * WID + x0) * 32;
    #pragma unroll
    for (int nt = 0; nt < 4; nt++) {
        int n = nt * 8 + 2 * tig;
        float bv0 = __ldg(bias + n), bv1 = __ldg(bias + n + 1);
        #pragma unroll
        for (int mt = 0; mt < 2; mt++)
            #pragma unroll
            for (int hh = 0; hh < 2; hh++) {
                int x = qid + mt * 16 + hh * 8;
                float v0 = fmaxf(acc[mt][nt][hh * 2 + 0] + bv0, 0.f);
                float v1 = fmaxf(acc[mt][nt][hh * 2 + 1] + bv1, 0.f);
                *(__half2*)(ob + (size_t)x * 32 + n) = __floats2half2_rn(v0, v1);
            }
    }
}

// ---------------- conv4: 32->1 via mma (N=8, col 0 real), fused final ----------------
// 512 thr, tile 16x32; warp = row, M=32 (2 mt). No cvt in staging (raw half copy).
__global__ void __launch_bounds__(512, 3) conv4_mma(
    const __half* __restrict__ a3, const __half* __restrict__ w4p,
    const float* __restrict__ b4, const float* __restrict__ sf,
    float* __restrict__ out)
{
    constexpr int AS = 40;
    extern __shared__ char smraw[];
    __half* s_act = (__half*)smraw;          // 612*40*2 = 48960 B
    char*   s_wb  = smraw + 48960;           // 4608 B

    const int tid = threadIdx.x;
    const int b   = blockIdx.z;
    const int x0  = blockIdx.x * 32;
    const int y0  = blockIdx.y * 16;

    const __half* inb = a3 + (size_t)b * HW * 32;
    for (int i = tid; i < 612 * 4; i += 512) {
        int px = i >> 2, j = i & 3;
        int yy = px / 34, xx = px - yy * 34;
        int gy = y0 - 1 + yy, gx = x0 - 1 + xx;
        uint4 v = {0u, 0u, 0u, 0u};
        if ((unsigned)gy < HGT && (unsigned)gx < WID)
            v = *(const uint4*)(inb + (size_t)(gy * WID + gx) * 32 + j * 8);
        *(uint4*)(s_act + px * AS + j * 8) = v;
    }
    for (int i = tid; i < 576; i += 512)
        ((uint64_t*)s_wb)[i] = ((const uint64_t*)w4p)[i];
    __syncthreads();

    const int warp = tid >> 5, lane = tid & 31;
    const int qid = lane >> 2, tig = lane & 3;

    float acc[2][4];
    #pragma unroll
    for (int mt = 0; mt < 2; mt++)
        #pragma unroll
        for (int u = 0; u < 4; u++) acc[mt][u] = 0.f;

    #pragma unroll 1
    for (int tap = 0; tap < 9; tap++) {
        const int pxb = (warp + tap / 3) * 34 + tap % 3 + qid;
        #pragma unroll
        for (int kk = 0; kk < 2; kk++) {
            uint32_t a[2][4];
            #pragma unroll
            for (int mt = 0; mt < 2; mt++) {
                const __half* ap = s_act + (pxb + mt * 16) * AS + kk * 16 + 2 * tig;
                a[mt][0] = *(const uint32_t*)(ap);
                a[mt][1] = *(const uint32_t*)(ap + 8 * AS);
                a[mt][2] = *(const uint32_t*)(ap + 8);
                a[mt][3] = *(const uint32_t*)(ap + 8 * AS + 8);
            }
            uint2 B0 = *(const uint2*)(s_wb + (tap * 2 + kk) * 256 + lane * 8);
            MMA_F16(acc[0], a[0], B0.x, B0.y);
            MMA_F16(acc[1], a[1], B0.x, B0.y);
        }
    }

    // epilogue: col 0 lives in lanes tig==0 (c[0]=row qid, c[2]=row qid+8)
    if (tig == 0) {
        const float sfv = sf[0], b4v = b4[0];
        #pragma unroll
        for (int mt = 0; mt < 2; mt++)
            #pragma unroll
            for (int hh = 0; hh < 2; hh++) {
                int x = x0 + mt * 16 + hh * 8 + qid;
                size_t idx = (size_t)b * HW + (size_t)(y0 + warp) * WID + x;
                float vh = (acc[mt][hh * 2] + b4v) * sfv;
                out[5 * (size_t)BHW + idx] = vh;                 // V_hat
                out[idx] = out[(size_t)BHW + idx] + vh;          // outputs = H + V_hat
            }
    }
}

// ---------------- launch ----------------
extern "C" void kernel_launch(void* const* d_in, const int* in_sizes, int n_in,
                              void* d_out, int out_size)
{
    const float* inputs = (const float*)d_in[0];
    const float* H0     = (const float*)d_in[1];
    const float* C0     = (const float*)d_in[2];
    const float* c2     = (const float*)d_in[3];
    const float* sf     = (const float*)d_in[4];
    const float* w1     = (const float*)d_in[5];
    const float* b1     = (const float*)d_in[6];
    const float* w2     = (const float*)d_in[7];
    const float* b2     = (const float*)d_in[8];
    const float* w3     = (const float*)d_in[9];
    const float* b3     = (const float*)d_in[10];
    const float* w4     = (const float*)d_in[11];
    const float* b4     = (const float*)d_in[12];
    float* out = (float*)d_out;

    __half *actAh, *actBh, *actCh, *w1p, *w2p, *w3p, *w4p;
    cudaGetSymbolAddress((void**)&actAh, g_actAh);
    cudaGetSymbolAddress((void**)&actBh, g_actBh);
    cudaGetSymbolAddress((void**)&actCh, g_actCh);
    cudaGetSymbolAddress((void**)&w1p,   g_w1p);
    cudaGetSymbolAddress((void**)&w2p,   g_w2p);
    cudaGetSymbolAddress((void**)&w3p,   g_w3p);
    cudaGetSymbolAddress((void**)&w4p,   g_w4p);

    const int SM2 = 48960 + 36864;   // 85824, 1 CTA/SM
    const int SM3 = 48960 + 18432;   // 67392 -> 2 CTAs/SM
    const int SM4 = 48960 + 4608;    // 53568 -> 3 CTAs/SM

    cudaFuncSetAttribute(conv2_mma, cudaFuncAttributeMaxDynamicSharedMemorySize, SM2);
    cudaFuncSetAttribute(conv3_mma, cudaFuncAttributeMaxDynamicSharedMemorySize, SM3);
    cudaFuncSetAttribute(conv4_mma, cudaFuncAttributeMaxDynamicSharedMemorySize, SM4);

    w_pack_k<<<144, 256>>>(w1, w2, w3, w4, w1p, w2p, w3p, w4p);

    dim3 pg(WID / 16, HGT / 16, BATCH);   // (16, 16, 8)
    fuse_pc1_k<<<pg, 256>>>(inputs, H0, C0, c2, sf, w1p, b1, out, actAh);

    dim3 tcg(WID / 32, HGT / 16, BATCH);  // (8, 16, 8)
    conv2_mma<<<tcg, 1024, SM2>>>(actAh, w2p, b2, actBh);
    conv3_mma<<<tcg,  512, SM3>>>(actBh, w3p, b3, actCh);
    conv4_mma<<<tcg,  512, SM4>>>(actCh, w4p, b4, sf, out);
}

// round 17
// speedup vs baseline: 1.2599x; 1.0116x over previous
#include <cuda_runtime.h>
#include <cuda_fp16.h>
#include <cstdint>

#define WID 256
#define HGT 256
#define HW  65536
#define BATCH 8
#define BHW 524288

// ---------------- scratch ----------------
__device__ __half g_actAh[(size_t)BATCH * HW * 32];  // conv1 out (half, NHWC)
__device__ __half g_actBh[(size_t)BATCH * HW * 64];  // conv2 out (half, NHWC)
__device__ __half g_actCh[(size_t)BATCH * HW * 32];  // conv3 out (half, NHWC)
__device__ __half g_w1p[512];                        // conv1 w packed, 1KB block
__device__ __half g_w2p[9 * 2 * 2 * 512];            // conv2 w packed (tap,kk,nh) 1KB blocks
__device__ __half g_w3p[2 * 9 * 2 * 2 * 512];        // conv3 w packed (h,tap,kk) 1KB blocks
__device__ __half g_w4p[9 * 2 * 128];                // conv4 w packed (tap,kk) 256B blocks

// ---------------- helpers ----------------
#define MMA_F16(d, a, b0, b1) \
    asm volatile("mma.sync.aligned.m16n8k16.row.col.f32.f16.f16.f32 " \
        "{%0,%1,%2,%3}, {%4,%5,%6,%7}, {%8,%9}, {%0,%1,%2,%3};" \
        : "+f"((d)[0]), "+f"((d)[1]), "+f"((d)[2]), "+f"((d)[3]) \
        : "r"((a)[0]), "r"((a)[1]), "r"((a)[2]), "r"((a)[3]), "r"(b0), "r"(b1))

#define LDSM_X4(R, addr) \
    asm volatile("ldmatrix.sync.aligned.m8n8.x4.shared.b16 {%0,%1,%2,%3}, [%4];" \
        : "=r"((R)[0]), "=r"((R)[1]), "=r"((R)[2]), "=r"((R)[3]) : "r"(addr))

__device__ __forceinline__ uint32_t cvta_smem(const void* p) {
    uint32_t a;
    asm("{ .reg .u64 t; cvta.to.shared.u64 t, %1; cvt.u32.u64 %0, t; }" : "=r"(a) : "l"(p));
    return a;
}

// ---------------- weight pack: fp16, exact fragment order ----------------
__global__ void __launch_bounds__(256) w_pack_k(
    const float* __restrict__ w1, const float* __restrict__ w2,
    const float* __restrict__ w3, const float* __restrict__ w4,
    __half* __restrict__ p1, __half* __restrict__ p2,
    __half* __restrict__ p3, __half* __restrict__ p4)
{
    int idx = blockIdx.x * 256 + threadIdx.x;   // < 36864
    if (idx < 512) {     // conv1: single kk block, K=16 (9 taps + pad)
        int e = idx & 7, lane = (idx >> 3) & 31, blk = (idx >> 8) & 1;
        int qid = lane >> 2, tig = lane & 3;
        int nt = blk * 2 + (e >> 2), breg = (e >> 1) & 1, lo = e & 1;
        int k = breg * 8 + 2 * tig + lo;
        int n = nt * 8 + qid;
        p1[(blk * 32 + lane) * 8 + e] =
            (k < 9) ? __float2half_rn(w1[n * 9 + k]) : __half(0.f);
    }
    if (idx < 2304) {    // conv4: (tap,kk) 256B blocks, N=8 (only n=0 real)
        int e = idx & 3, lane = (idx >> 2) & 31;
        int kk = (idx >> 7) & 1, tap = idx >> 8;
        int qid = lane >> 2, tig = lane & 3;
        int breg = e >> 1, lo = e & 1;
        int k = kk * 16 + breg * 8 + 2 * tig + lo;
        p4[((tap * 2 + kk) * 32 + lane) * 4 + e] =
            (qid == 0) ? __float2half_rn(w4[k * 9 + tap]) : __half(0.f);
    }
    if (idx < 18432) {   // conv2: nh-split (N=32 per warp), 1KB blocks
        int e = idx & 7, lane = (idx >> 3) & 31;
        int blk = (idx >> 8) & 1, nh = (idx >> 9) & 1;
        int kk = (idx >> 10) & 1, tap = idx >> 11;
        int qid = lane >> 2, tig = lane & 3;
        int nt = blk * 2 + (e >> 2), breg = (e >> 1) & 1, lo = e & 1;
        int k = kk * 16 + breg * 8 + 2 * tig + lo;
        int n = nh * 32 + nt * 8 + qid;
        p2[((((tap * 2 + kk) * 2 + nh) * 2 + blk) * 32 + lane) * 8 + e] =
            __float2half_rn(w2[((size_t)n * 32 + k) * 9 + tap]);
    }
    {   // conv3: full-n, cin-half h, 1KB blocks
        int h = idx / 18432, r = idx - h * 18432;
        int tap = r / 2048, r2 = r - tap * 2048;
        int kk = (r2 >> 10) & 1, blk = (r2 >> 9) & 1;
        int lane = (r2 >> 3) & 31, e = r2 & 7;
        int qid = lane >> 2, tig = lane & 3;
        int nt = blk * 2 + (e >> 2), breg = (e >> 1) & 1, lo = e & 1;
        int k = h * 32 + kk * 16 + breg * 8 + 2 * tig + lo;
        int n = nt * 8 + qid;
        p3[(size_t)h * 18432 +
           (((tap * 2 + kk) * 2 + blk) * 32 + lane) * 8 + e] =
            __float2half_rn(w3[((size_t)n * 64 + k) * 9 + tap]);
    }
}

// ---------------- fused prep + conv1 (mma, R15 proven) ----------------
__global__ void __launch_bounds__(256) fuse_pc1_k(
    const float* __restrict__ inp, const float* __restrict__ H0,
    const float* __restrict__ C0, const float* __restrict__ c2,
    const float* __restrict__ sf, const __half* __restrict__ w1p,
    const float* __restrict__ b1, float* __restrict__ out,
    __half* __restrict__ actA)
{
    __shared__ float  s_in[324];
    __shared__ float  s_vs[324];
    __shared__ __half s_a[256 * 20];
    __shared__ __half s_w1[512];
    __shared__ float  sb[32];

    const int tid = threadIdx.x;
    const int b = blockIdx.z, x0 = blockIdx.x * 16, y0 = blockIdx.y * 16;

    if (tid < 32) sb[tid] = b1[tid];
    if (tid < 64) ((uint4*)s_w1)[tid] = ((const uint4*)w1p)[tid];
    const float sfv = sf[0];

    for (int i = tid; i < 324; i += 256) {
        int yy = i / 18, xx = i - yy * 18;
        int gy = y0 - 1 + yy, gx = x0 - 1 + xx;
        float iv = 0.f, vsv = 0.f;
        if ((unsigned)gy < HGT && (unsigned)gx < WID) {
            int gidx = (b << 16) + (gy << 8) + gx;
            iv  = inp[gidx];
            vsv = (iv - H0[gidx]) / sfv;
        }
        s_in[i] = iv;
        s_vs[i] = vsv;
    }
    __syncthreads();

    const int py = tid >> 4, px = tid & 15;
    const int si = (py + 1) * 18 + px + 1;
    const int rem = ((y0 + py) << 8) + x0 + px;
    const int idx = (b << 16) + rem;

    float cc  = s_in[si];
    float lap = s_in[si - 18] + s_in[si + 18] + s_in[si - 1] + s_in[si + 1] - 4.f * cc;
    float c0v = C0[(size_t)b * 2 * HW + rem];
    float Hv  = 2.f * cc - c0v + c2[0] * lap;
    float V   = cc - H0[idx];

    out[(size_t)BHW + idx]     = Hv;
    out[4 * (size_t)BHW + idx] = V;
    out[2 * (size_t)BHW + (size_t)b * 2 * HW + rem]      = cc;
    out[2 * (size_t)BHW + (size_t)b * 2 * HW + HW + rem] = c0v;

    {
        __half* ap = s_a + tid * 20;
        #pragma unroll
        for (int t = 0; t < 9; t++)
            ap[t] = __float2half_rn(s_vs[(py + t / 3) * 18 + px + t % 3]);
        #pragma unroll
        for (int t = 9; t < 16; t++) ap[t] = __half(0.f);
    }
    __syncthreads();

    const int warp = tid >> 5, lane = tid & 31;
    const int qid = lane >> 2, tig = lane & 3;

    float acc[2][4][4];
    #pragma unroll
    for (int mt = 0; mt < 2; mt++)
        #pragma unroll
        for (int nt = 0; nt < 4; nt++)
            #pragma unroll
            for (int u = 0; u < 4; u++) acc[mt][nt][u] = 0.f;

    uint32_t a[2][4];
    #pragma unroll
    for (int mt = 0; mt < 2; mt++) {
        const __half* ap = s_a + (warp * 32 + mt * 16 + qid) * 20 + 2 * tig;
        a[mt][0] = *(const uint32_t*)(ap);
        a[mt][1] = *(const uint32_t*)(ap + 8 * 20);
        a[mt][2] = *(const uint32_t*)(ap + 8);
        a[mt][3] = *(const uint32_t*)(ap + 8 * 20 + 8);
    }
    {
        const char* wb = (const char*)s_w1 + lane * 16;
        uint4 B0 = *(const uint4*)wb;
        uint4 B1 = *(const uint4*)(wb + 512);
        #pragma unroll
        for (int mt = 0; mt < 2; mt++) {
            MMA_F16(acc[mt][0], a[mt], B0.x, B0.y);
            MMA_F16(acc[mt][1], a[mt], B0.z, B0.w);
            MMA_F16(acc[mt][2], a[mt], B1.x, B1.y);
            MMA_F16(acc[mt][3], a[mt], B1.z, B1.w);
        }
    }

    #pragma unroll
    for (int nt = 0; nt < 4; nt++) {
        int n = nt * 8 + 2 * tig;
        float bv0 = sb[n], bv1 = sb[n + 1];
        #pragma unroll
        for (int mt = 0; mt < 2; mt++)
            #pragma unroll
            for (int hh = 0; hh < 2; hh++) {
                int p = warp * 32 + mt * 16 + hh * 8 + qid;
                int gpx = ((b << 16) + ((y0 + (p >> 4)) << 8) + x0 + (p & 15));
                float v0 = fmaxf(acc[mt][nt][hh * 2 + 0] + bv0, 0.f);
                float v1 = fmaxf(acc[mt][nt][hh * 2 + 1] + bv1, 0.f);
                *(__half2*)(actA + (size_t)gpx * 32 + n) = __floats2half2_rn(v0, v1);
            }
    }
}

// ---------------- conv2: 32->64 fp16 mma k16, 1024 thr, n-split, LDSM A ----------------
__global__ void __launch_bounds__(1024, 1) conv2_mma(
    const __half* __restrict__ in, const __half* __restrict__ wp,
    const float* __restrict__ bias, __half* __restrict__ outp)
{
    constexpr int AS = 40;
    extern __shared__ char smraw[];
    __half* s_act = (__half*)smraw;          // 48960 B
    char*   s_wb  = smraw + 48960;           // 36864 B

    const int tid = threadIdx.x;
    const int b   = blockIdx.z;
    const int x0  = blockIdx.x * 32;
    const int y0  = blockIdx.y * 16;

    const __half* inb = in + (size_t)b * HW * 32;
    for (int i = tid; i < 612 * 4; i += 1024) {
        int px = i >> 2, j = i & 3;
        int yy = px / 34, xx = px - yy * 34;
        int gy = y0 - 1 + yy, gx = x0 - 1 + xx;
        uint4 v = {0u, 0u, 0u, 0u};
        if ((unsigned)gy < HGT && (unsigned)gx < WID)
            v = *(const uint4*)(inb + (size_t)(gy * WID + gx) * 32 + j * 8);
        *(uint4*)(s_act + px * AS + j * 8) = v;
    }
    for (int i = tid; i < 2304; i += 1024)
        ((uint4*)s_wb)[i] = ((const uint4*)wp)[i];
    __syncthreads();

    const int warp = tid >> 5, lane = tid & 31;
    const int row = warp >> 1, nh = warp & 1;
    const int qid = lane >> 2, tig = lane & 3;
    // ldmatrix lane base: row (lane&15), k-half (lane>>4)
    const uint32_t lds_base = cvta_smem(s_act) + (lane & 15) * (AS * 2) + (lane >> 4) * 16;

    float acc[2][4][4];
    #pragma unroll
    for (int mt = 0; mt < 2; mt++)
        #pragma unroll
        for (int nt = 0; nt < 4; nt++)
            #pragma unroll
            for (int u = 0; u < 4; u++) acc[mt][nt][u] = 0.f;

    #pragma unroll 1
    for (int tap = 0; tap < 9; tap++) {
        const uint32_t tap_base = lds_base +
            ((row + tap / 3) * 34 + tap % 3) * (AS * 2);
        #pragma unroll
        for (int kk = 0; kk < 2; kk++) {
            uint32_t a[2][4];
            LDSM_X4(a[0], tap_base + kk * 32);
            LDSM_X4(a[1], tap_base + 16 * (AS * 2) + kk * 32);
            const char* wb = s_wb + ((tap * 2 + kk) * 2 + nh) * 1024 + lane * 16;
            uint4 B0 = *(const uint4*)wb;
            uint4 B1 = *(const uint4*)(wb + 512);
            #pragma unroll
            for (int mt = 0; mt < 2; mt++) {
                MMA_F16(acc[mt][0], a[mt], B0.x, B0.y);
                MMA_F16(acc[mt][1], a[mt], B0.z, B0.w);
                MMA_F16(acc[mt][2], a[mt], B1.x, B1.y);
                MMA_F16(acc[mt][3], a[mt], B1.z, B1.w);
            }
        }
    }

    __half* ob = outp + ((size_t)b * HW + (size_t)(y0 + row) * WID + x0) * 64;
    #pragma unroll
    for (int nt = 0; nt < 4; nt++) {
        int n = nh * 32 + nt * 8 + 2 * tig;
        float bv0 = __ldg(bias + n), bv1 = __ldg(bias + n + 1);
        #pragma unroll
        for (int mt = 0; mt < 2; mt++)
            #pragma unroll
            for (int hh = 0; hh < 2; hh++) {
                int x = qid + mt * 16 + hh * 8;
                float v0 = fmaxf(acc[mt][nt][hh * 2 + 0] + bv0, 0.f);
                float v1 = fmaxf(acc[mt][nt][hh * 2 + 1] + bv1, 0.f);
                *(__half2*)(ob + (size_t)x * 64 + n) = __floats2half2_rn(v0, v1);
            }
    }
}

// ---------------- conv3: full-n, 512 thr, 2 CTAs/SM, half out, LDSM A ----------------
__global__ void __launch_bounds__(512, 2) conv3_mma(
    const __half* __restrict__ in, const __half* __restrict__ wp,
    const float* __restrict__ bias, __half* __restrict__ outp)
{
    constexpr int AS = 40;
    extern __shared__ char smraw[];
    __half* s_act = (__half*)smraw;          // 48960 B
    char*   s_wb  = smraw + 48960;           // 18432 B

    const int tid = threadIdx.x;
    const int b   = blockIdx.z;
    const int x0  = blockIdx.x * 32;
    const int y0  = blockIdx.y * 16;

    const __half* inb = in + (size_t)b * HW * 64;
    const int warp = tid >> 5, lane = tid & 31;
    const int qid = lane >> 2, tig = lane & 3;
    const uint32_t lds_base = cvta_smem(s_act) + (lane & 15) * (AS * 2) + (lane >> 4) * 16;

    float acc[2][4][4];
    #pragma unroll
    for (int mt = 0; mt < 2; mt++)
        #pragma unroll
        for (int nt = 0; nt < 4; nt++)
            #pragma unroll
            for (int u = 0; u < 4; u++) acc[mt][nt][u] = 0.f;

    #pragma unroll 1
    for (int h = 0; h < 2; h++) {
        if (h) __syncthreads();
        for (int i = tid; i < 612 * 4; i += 512) {
            int px = i >> 2, j = i & 3;
            int yy = px / 34, xx = px - yy * 34;
            int gy = y0 - 1 + yy, gx = x0 - 1 + xx;
            uint4 v = {0u, 0u, 0u, 0u};
            if ((unsigned)gy < HGT && (unsigned)gx < WID)
                v = *(const uint4*)(inb + (size_t)(gy * WID + gx) * 64 + h * 32 + j * 8);
            *(uint4*)(s_act + px * AS + j * 8) = v;
        }
        for (int i = tid; i < 1152; i += 512)
            ((uint4*)s_wb)[i] = ((const uint4*)(wp + (size_t)h * 18432))[i];
        __syncthreads();

        #pragma unroll 1
        for (int tap = 0; tap < 9; tap++) {
            const uint32_t tap_base = lds_base +
                ((warp + tap / 3) * 34 + tap % 3) * (AS * 2);
            #pragma unroll
            for (int kk = 0; kk < 2; kk++) {
                uint32_t a[2][4];
                LDSM_X4(a[0], tap_base + kk * 32);
                LDSM_X4(a[1], tap_base + 16 * (AS * 2) + kk * 32);
                const char* wb = s_wb + (tap * 2 + kk) * 1024 + lane * 16;
                uint4 B0 = *(const uint4*)wb;
                uint4 B1 = *(const uint4*)(wb + 512);
                #pragma unroll
                for (int mt = 0; mt < 2; mt++) {
                    MMA_F16(acc[mt][0], a[mt], B0.x, B0.y);
                    MMA_F16(acc[mt][1], a[mt], B0.z, B0.w);
                    MMA_F16(acc[mt][2], a[mt], B1.x, B1.y);
                    MMA_F16(acc[mt][3], a[mt], B1.z, B1.w);
                }
            }
        }
    }

    __half* ob = outp + ((size_t)b * HW + (size_t)(y0 + warp) * WID + x0) * 32;
    #pragma unroll
    for (int nt = 0; nt < 4; nt++) {
        int n = nt * 8 + 2 * tig;
        float bv0 = __ldg(bias + n), bv1 = __ldg(bias + n + 1);
        #pragma unroll
        for (int mt = 0; mt < 2; mt++)
            #pragma unroll
            for (int hh = 0; hh < 2; hh++) {
                int x = qid + mt * 16 + hh * 8;
                float v0 = fmaxf(acc[mt][nt][hh * 2 + 0] + bv0, 0.f);
                float v1 = fmaxf(acc[mt][nt][hh * 2 + 1] + bv1, 0.f);
                *(__half2*)(ob + (size_t)x * 32 + n) = __floats2half2_rn(v0, v1);
            }
    }
}

// ---------------- conv4: 32->1 via mma (N=8), fused final, LDSM A ----------------
__global__ void __launch_bounds__(512, 3) conv4_mma(
    const __half* __restrict__ a3, const __half* __restrict__ w4p,
    const float* __restrict__ b4, const float* __restrict__ sf,
    float* __restrict__ out)
{
    constexpr int AS = 40;
    extern __shared__ char smraw[];
    __half* s_act = (__half*)smraw;          // 48960 B
    char*   s_wb  = smraw + 48960;           // 4608 B

    const int tid = threadIdx.x;
    const int b   = blockIdx.z;
    const int x0  = blockIdx.x * 32;
    const int y0  = blockIdx.y * 16;

    const __half* inb = a3 + (size_t)b * HW * 32;
    for (int i = tid; i < 612 * 4; i += 512) {
        int px = i >> 2, j = i & 3;
        int yy = px / 34, xx = px - yy * 34;
        int gy = y0 - 1 + yy, gx = x0 - 1 + xx;
        uint4 v = {0u, 0u, 0u, 0u};
        if ((unsigned)gy < HGT && (unsigned)gx < WID)
            v = *(const uint4*)(inb + (size_t)(gy * WID + gx) * 32 + j * 8);
        *(uint4*)(s_act + px * AS + j * 8) = v;
    }
    for (int i = tid; i < 576; i += 512)
        ((uint64_t*)s_wb)[i] = ((const uint64_t*)w4p)[i];
    __syncthreads();

    const int warp = tid >> 5, lane = tid & 31;
    const int qid = lane >> 2, tig = lane & 3;
    const uint32_t lds_base = cvta_smem(s_act) + (lane & 15) * (AS * 2) + (lane >> 4) * 16;

    float acc[2][4];
    #pragma unroll
    for (int mt = 0; mt < 2; mt++)
        #pragma unroll
        for (int u = 0; u < 4; u++) acc[mt][u] = 0.f;

    #pragma unroll 1
    for (int tap = 0; tap < 9; tap++) {
        const uint32_t tap_base = lds_base +
            ((warp + tap / 3) * 34 + tap % 3) * (AS * 2);
        #pragma unroll
        for (int kk = 0; kk < 2; kk++) {
            uint32_t a[2][4];
            LDSM_X4(a[0], tap_base + kk * 32);
            LDSM_X4(a[1], tap_base + 16 * (AS * 2) + kk * 32);
            uint2 B0 = *(const uint2*)(s_wb + (tap * 2 + kk) * 256 + lane * 8);
            MMA_F16(acc[0], a[0], B0.x, B0.y);
            MMA_F16(acc[1], a[1], B0.x, B0.y);
        }
    }

    if (tig == 0) {
        const float sfv = sf[0], b4v = b4[0];
        #pragma unroll
        for (int mt = 0; mt < 2; mt++)
            #pragma unroll
            for (int hh = 0; hh < 2; hh++) {
                int x = x0 + mt * 16 + hh * 8 + qid;
                size_t idx = (size_t)b * HW + (size_t)(y0 + warp) * WID + x;
                float vh = (acc[mt][hh * 2] + b4v) * sfv;
                out[5 * (size_t)BHW + idx] = vh;                 // V_hat
                out[idx] = out[(size_t)BHW + idx] + vh;          // outputs
            }
    }
}

// ---------------- launch ----------------
extern "C" void kernel_launch(void* const* d_in, const int* in_sizes, int n_in,
                              void* d_out, int out_size)
{
    const float* inputs = (const float*)d_in[0];
    const float* H0     = (const float*)d_in[1];
    const float* C0     = (const float*)d_in[2];
    const float* c2     = (const float*)d_in[3];
    const float* sf     = (const float*)d_in[4];
    const float* w1     = (const float*)d_in[5];
    const float* b1     = (const float*)d_in[6];
    const float* w2     = (const float*)d_in[7];
    const float* b2     = (const float*)d_in[8];
    const float* w3     = (const float*)d_in[9];
    const float* b3     = (const float*)d_in[10];
    const float* w4     = (const float*)d_in[11];
    const float* b4     = (const float*)d_in[12];
    float* out = (float*)d_out;

    __half *actAh, *actBh, *actCh, *w1p, *w2p, *w3p, *w4p;
    cudaGetSymbolAddress((void**)&actAh, g_actAh);
    cudaGetSymbolAddress((void**)&actBh, g_actBh);
    cudaGetSymbolAddress((void**)&actCh, g_actCh);
    cudaGetSymbolAddress((void**)&w1p,   g_w1p);
    cudaGetSymbolAddress((void**)&w2p,   g_w2p);
    cudaGetSymbolAddress((void**)&w3p,   g_w3p);
    cudaGetSymbolAddress((void**)&w4p,   g_w4p);

    const int SM2 = 48960 + 36864;   // 85824, 1 CTA/SM
    const int SM3 = 48960 + 18432;   // 67392 -> 2 CTAs/SM
    const int SM4 = 48960 + 4608;    // 53568 -> 3 CTAs/SM

    cudaFuncSetAttribute(conv2_mma, cudaFuncAttributeMaxDynamicSharedMemorySize, SM2);
    cudaFuncSetAttribute(conv3_mma, cudaFuncAttributeMaxDynamicSharedMemorySize, SM3);
    cudaFuncSetAttribute(conv4_mma, cudaFuncAttributeMaxDynamicSharedMemorySize, SM4);

    w_pack_k<<<144, 256>>>(w1, w2, w3, w4, w1p, w2p, w3p, w4p);

    dim3 pg(WID / 16, HGT / 16, BATCH);   // (16, 16, 8)
    fuse_pc1_k<<<pg, 256>>>(inputs, H0, C0, c2, sf, w1p, b1, out, actAh);

    dim3 tcg(WID / 32, HGT / 16, BATCH);  // (8, 16, 8)
    conv2_mma<<<tcg, 1024, SM2>>>(actAh, w2p, b2, actBh);
    conv3_mma<<<tcg,  512, SM3>>>(actBh, w3p, b3, actCh);
    conv4_mma<<<tcg,  512, SM4>>>(actCh, w4p, b4, sf, out);
}